// round 1
// baseline (speedup 1.0000x reference)
#include <cuda_runtime.h>
#include <math.h>

// Problem constants
#define NBATCH 4
#define SEQ    2048
#define DMODEL 512
#define DFFN   2048
#define BSTOT  (NBATCH*SEQ)   // 8192 rows

// ---------------- scratch (allocation-free: __device__ globals) ----------------
__device__ float g_x [BSTOT*DMODEL];
__device__ float g_k [BSTOT*DMODEL];
__device__ float g_q [BSTOT*DMODEL];
__device__ float g_v [BSTOT*DMODEL];
__device__ float g_at[BSTOT*DMODEL];
__device__ float g_r [BSTOT*DMODEL];
__device__ float g_f2[BSTOT*DMODEL];
__device__ float g_sc[NBATCH*SEQ*SEQ];    // 67 MB attention scores
__device__ float g_f1[BSTOT*DFFN];        // 67 MB ffn hidden

// ---------------- GEMM: 128x128x8 tile, 8x8 microtile, 256 threads ----------------
// C[M,N] = act( alpha * A[M,K] @ B + bias )   ; B is [K,N] (NN) or [N,K] (NT)
// All of M,N divisible by 128 and K by 8 in this problem -> no bounds checks.
#define BM 128
#define BN 128
#define BK 8

template<bool TRANSB, int ACT, bool BIAS>
__global__ void __launch_bounds__(256, 2)
gemm_kernel(const float* __restrict__ A, const float* __restrict__ B,
            const float* __restrict__ bias, float* __restrict__ C,
            int M, int N, int K, float alpha,
            long long strideA, long long strideB, long long strideC)
{
    A += (long long)blockIdx.z * strideA;
    B += (long long)blockIdx.z * strideB;
    C += (long long)blockIdx.z * strideC;

    __shared__ float As[BK][BM + 4];
    __shared__ float Bs[BK][BN + 4];

    const int tid = threadIdx.x;
    const int tx  = tid & 15;        // 0..15 -> N direction
    const int ty  = tid >> 4;        // 0..15 -> M direction
    const int bm  = blockIdx.y * BM;
    const int bn  = blockIdx.x * BN;

    // A load: float4 along K. row = tid/2 (0..127), k = (tid&1)*4
    const int ldRow = tid >> 1;
    const int ldK   = (tid & 1) * 4;
    // B NN load: float4 along N. k = tid/32, col = (tid&31)*4
    const int bK    = tid >> 5;
    const int bCol  = (tid & 31) * 4;

    const float* Aptr = A + (long long)(bm + ldRow) * K + ldK;
    const float* Bptr = TRANSB ? (B + (long long)(bn + ldRow) * K + ldK)
                               : (B + (long long)bK * N + bn + bCol);

    float acc[8][8];
    #pragma unroll
    for (int i = 0; i < 8; i++)
        #pragma unroll
        for (int j = 0; j < 8; j++) acc[i][j] = 0.f;

    const int ktiles = K / BK;
    float4 av = *(const float4*)Aptr;
    float4 bv = *(const float4*)Bptr;

    for (int t = 0; t < ktiles; ++t) {
        // stage current tile into smem
        As[ldK + 0][ldRow] = av.x;
        As[ldK + 1][ldRow] = av.y;
        As[ldK + 2][ldRow] = av.z;
        As[ldK + 3][ldRow] = av.w;
        if (TRANSB) {
            Bs[ldK + 0][ldRow] = bv.x;
            Bs[ldK + 1][ldRow] = bv.y;
            Bs[ldK + 2][ldRow] = bv.z;
            Bs[ldK + 3][ldRow] = bv.w;
        } else {
            *(float4*)&Bs[bK][bCol] = bv;
        }
        __syncthreads();

        // prefetch next tile into registers while computing
        Aptr += BK;
        Bptr += TRANSB ? BK : (long long)BK * N;
        float4 avn = av, bvn = bv;
        if (t + 1 < ktiles) {
            avn = *(const float4*)Aptr;
            bvn = *(const float4*)Bptr;
        }

        #pragma unroll
        for (int kk = 0; kk < BK; ++kk) {
            float a[8], b[8];
            *(float4*)&a[0] = *(const float4*)&As[kk][ty * 8];
            *(float4*)&a[4] = *(const float4*)&As[kk][ty * 8 + 4];
            *(float4*)&b[0] = *(const float4*)&Bs[kk][tx * 8];
            *(float4*)&b[4] = *(const float4*)&Bs[kk][tx * 8 + 4];
            #pragma unroll
            for (int i = 0; i < 8; i++)
                #pragma unroll
                for (int j = 0; j < 8; j++)
                    acc[i][j] = fmaf(a[i], b[j], acc[i][j]);
        }
        __syncthreads();
        av = avn; bv = bvn;
    }

    // epilogue
    float bb[8];
    #pragma unroll
    for (int j = 0; j < 8; j++)
        bb[j] = BIAS ? bias[bn + tx * 8 + j] : 0.f;

    #pragma unroll
    for (int i = 0; i < 8; i++) {
        long long row = bm + ty * 8 + i;
        float* Crow = C + row * N + bn + tx * 8;
        float o[8];
        #pragma unroll
        for (int j = 0; j < 8; j++) {
            float vv = acc[i][j] * alpha + bb[j];
            if (ACT == 1) // exact GELU: x * 0.5 * (1 + erf(x / sqrt(2)))
                vv = 0.5f * vv * (1.0f + erff(vv * 0.7071067811865475f));
            o[j] = vv;
        }
        *(float4*)&Crow[0] = *(float4*)&o[0];
        *(float4*)&Crow[4] = *(float4*)&o[4];
    }
}

// ---------------- block reductions ----------------
template<int NT>
__device__ __forceinline__ float blockSum(float v, float* sm) {
    #pragma unroll
    for (int o = 16; o > 0; o >>= 1) v += __shfl_xor_sync(0xffffffffu, v, o);
    const int w = threadIdx.x >> 5;
    if ((threadIdx.x & 31) == 0) sm[w] = v;
    __syncthreads();
    if (threadIdx.x < 32) {
        float x = (threadIdx.x < NT / 32) ? sm[threadIdx.x] : 0.f;
        #pragma unroll
        for (int o = NT / 64; o > 0; o >>= 1) x += __shfl_xor_sync(0xffffffffu, x, o);
        if (threadIdx.x == 0) sm[0] = x;
    }
    __syncthreads();
    float r = sm[0];
    __syncthreads();
    return r;
}

template<int NT>
__device__ __forceinline__ float blockMax(float v, float* sm) {
    #pragma unroll
    for (int o = 16; o > 0; o >>= 1) v = fmaxf(v, __shfl_xor_sync(0xffffffffu, v, o));
    const int w = threadIdx.x >> 5;
    if ((threadIdx.x & 31) == 0) sm[w] = v;
    __syncthreads();
    if (threadIdx.x < 32) {
        float x = (threadIdx.x < NT / 32) ? sm[threadIdx.x] : -INFINITY;
        #pragma unroll
        for (int o = NT / 64; o > 0; o >>= 1) x = fmaxf(x, __shfl_xor_sync(0xffffffffu, x, o));
        if (threadIdx.x == 0) sm[0] = x;
    }
    __syncthreads();
    float r = sm[0];
    __syncthreads();
    return r;
}

// ---------------- embedding + positional ----------------
__global__ void embed_kernel(const int* __restrict__ seq,
                             const float* __restrict__ emb,
                             float* __restrict__ x)
{
    const int row = blockIdx.x;           // 0..8191
    const int s   = row & (SEQ - 1);
    const int tok = seq[row];
    const float sc = 22.62741699796952f;  // sqrt(512)
    const int d0 = threadIdx.x * 4;       // 128 threads * 4
    #pragma unroll
    for (int j = 0; j < 4; j++) {
        const int d = d0 + j;
        // angle = s / 10000^(2d/512), even d -> sin, odd -> cos (computed in double)
        double ang = (double)s * exp(-(2.0 * (double)d / 512.0) * 9.210340371976184);
        double p   = ((d & 1) == 0) ? sin(ang) : cos(ang);
        x[(long long)row * DMODEL + d] =
            (emb[(long long)tok * DMODEL + d] + (float)p) * sc;
    }
}

// ---------------- softmax over rows of length SEQ ----------------
__global__ void softmax_kernel(float* __restrict__ S)
{
    __shared__ float sm[8];
    float* row = S + (long long)blockIdx.x * SEQ;
    const int t = threadIdx.x;            // 256 threads, 8 elems each, coalesced
    float vals[8];
    float m = -INFINITY;
    #pragma unroll
    for (int i = 0; i < 8; i++) { vals[i] = row[t + i * 256]; m = fmaxf(m, vals[i]); }
    m = blockMax<256>(m, sm);
    float s = 0.f;
    #pragma unroll
    for (int i = 0; i < 8; i++) { vals[i] = expf(vals[i] - m); s += vals[i]; }
    s = blockSum<256>(s, sm);
    const float inv = 1.f / s;
    #pragma unroll
    for (int i = 0; i < 8; i++) row[t + i * 256] = vals[i] * inv;
}

// ---------------- fused residual-add + LayerNorm over D=512 ----------------
__global__ void add_ln_kernel(const float* __restrict__ a,
                              const float* __restrict__ b,
                              const float* __restrict__ gamma,
                              const float* __restrict__ beta,
                              float* __restrict__ out)
{
    __shared__ float sm[4];
    const long long base = (long long)blockIdx.x * DMODEL;
    const int d0 = threadIdx.x * 4;       // 128 threads * 4
    float4 av = *(const float4*)(a + base + d0);
    float4 bv = *(const float4*)(b + base + d0);
    float z[4] = { av.x + bv.x, av.y + bv.y, av.z + bv.z, av.w + bv.w };
    float s = z[0] + z[1] + z[2] + z[3];
    s = blockSum<128>(s, sm);
    const float mu = s * (1.0f / DMODEL);
    float vs = 0.f;
    #pragma unroll
    for (int i = 0; i < 4; i++) { float dz = z[i] - mu; vs += dz * dz; }
    vs = blockSum<128>(vs, sm);
    const float rstd = rsqrtf(vs * (1.0f / DMODEL) + 1e-5f);
    float4 gv = *(const float4*)(gamma + d0);
    float4 bvv = *(const float4*)(beta + d0);
    float4 o;
    o.x = (z[0] - mu) * rstd * gv.x + bvv.x;
    o.y = (z[1] - mu) * rstd * gv.y + bvv.y;
    o.z = (z[2] - mu) * rstd * gv.z + bvv.z;
    o.w = (z[3] - mu) * rstd * gv.w + bvv.w;
    *(float4*)(out + base + d0) = o;
}

// ---------------- launch ----------------
extern "C" void kernel_launch(void* const* d_in, const int* in_sizes, int n_in,
                              void* d_out, int out_size)
{
    const int*   seq  = (const int*)  d_in[0];
    const float* emb  = (const float*)d_in[1];
    const float* wk   = (const float*)d_in[2];
    const float* bk   = (const float*)d_in[3];
    const float* wq   = (const float*)d_in[4];
    const float* bq   = (const float*)d_in[5];
    const float* wv   = (const float*)d_in[6];
    const float* bv   = (const float*)d_in[7];
    const float* ln_g = (const float*)d_in[8];
    const float* ln_b = (const float*)d_in[9];
    const float* w1   = (const float*)d_in[10];
    const float* b1   = (const float*)d_in[11];
    const float* w2   = (const float*)d_in[12];
    const float* b2   = (const float*)d_in[13];
    float* out = (float*)d_out;

    float *x, *k, *q, *v, *at, *r, *f2, *sc, *f1;
    cudaGetSymbolAddress((void**)&x,  g_x);
    cudaGetSymbolAddress((void**)&k,  g_k);
    cudaGetSymbolAddress((void**)&q,  g_q);
    cudaGetSymbolAddress((void**)&v,  g_v);
    cudaGetSymbolAddress((void**)&at, g_at);
    cudaGetSymbolAddress((void**)&r,  g_r);
    cudaGetSymbolAddress((void**)&f2, g_f2);
    cudaGetSymbolAddress((void**)&sc, g_sc);
    cudaGetSymbolAddress((void**)&f1, g_f1);

    // 1) x = (emb[seq] + pos) * sqrt(D)
    embed_kernel<<<BSTOT, 128>>>(seq, emb, x);

    // 2) projections (note reference swap: scores use k as Q, q as K)
    dim3 gp(DMODEL / BN, BSTOT / BM);     // (4, 64)
    gemm_kernel<false, 0, true><<<gp, 256>>>(x, wk, bk, k, BSTOT, DMODEL, DMODEL, 1.f, 0, 0, 0);
    gemm_kernel<false, 0, true><<<gp, 256>>>(x, wq, bq, q, BSTOT, DMODEL, DMODEL, 1.f, 0, 0, 0);
    gemm_kernel<false, 0, true><<<gp, 256>>>(x, wv, bv, v, BSTOT, DMODEL, DMODEL, 1.f, 0, 0, 0);

    // 3) scores[b,i,j] = k[b,i,:] . q[b,j,:] / sqrt(D)   (batched NT)
    dim3 gs(SEQ / BN, SEQ / BM, NBATCH);  // (16, 16, 4)
    gemm_kernel<true, 0, false><<<gs, 256>>>(k, q, nullptr, sc, SEQ, SEQ, DMODEL,
        0.04419417382415922f, (long long)SEQ * DMODEL, (long long)SEQ * DMODEL, (long long)SEQ * SEQ);

    // 4) softmax rows
    softmax_kernel<<<NBATCH * SEQ, 256>>>(sc);

    // 5) attn = P @ v  (batched NN)
    dim3 gv2(DMODEL / BN, SEQ / BM, NBATCH); // (4, 16, 4)
    gemm_kernel<false, 0, false><<<gv2, 256>>>(sc, v, nullptr, at, SEQ, DMODEL, SEQ,
        1.f, (long long)SEQ * SEQ, (long long)SEQ * DMODEL, (long long)SEQ * DMODEL);

    // 6) r = LN(x + attn)
    add_ln_kernel<<<BSTOT, 128>>>(x, at, ln_g, ln_b, r);

    // 7) f1 = gelu(r @ w1 + b1)
    dim3 gf1(DFFN / BN, BSTOT / BM);      // (16, 64)
    gemm_kernel<false, 1, true><<<gf1, 256>>>(r, w1, b1, f1, BSTOT, DFFN, DMODEL, 1.f, 0, 0, 0);

    // 8) f2 = f1 @ w2 + b2
    dim3 gf2(DMODEL / BN, BSTOT / BM);    // (4, 64)
    gemm_kernel<false, 0, true><<<gf2, 256>>>(f1, w2, b2, f2, BSTOT, DMODEL, DFFN, 1.f, 0, 0, 0);

    // 9) out = LN(r + f2)
    add_ln_kernel<<<BSTOT, 128>>>(r, f2, ln_g, ln_b, out);
}

// round 3
// speedup vs baseline: 1.6204x; 1.6204x over previous
#include <cuda_runtime.h>
#include <cstdint>
#include <math.h>

#define NBATCH 4
#define SEQ    2048
#define DMODEL 512
#define DFFN   2048
#define BSTOT  (NBATCH*SEQ)

// ---------------- scratch ----------------
__device__ float g_x  [BSTOT*DMODEL];
__device__ float g_k  [BSTOT*DMODEL];
__device__ float g_q  [BSTOT*DMODEL];
__device__ float g_v  [BSTOT*DMODEL];
__device__ float g_vT [BSTOT*DMODEL];
__device__ float g_at [BSTOT*DMODEL];
__device__ float g_r  [BSTOT*DMODEL];
__device__ float g_f2 [BSTOT*DMODEL];
__device__ float g_sc [(long long)NBATCH*SEQ*SEQ];
__device__ float g_f1 [(long long)BSTOT*DFFN];
__device__ float g_wkT[DMODEL*DMODEL];
__device__ float g_wqT[DMODEL*DMODEL];
__device__ float g_wvT[DMODEL*DMODEL];
__device__ float g_w1T[DFFN*DMODEL];
__device__ float g_w2T[DMODEL*DFFN];
__device__ float g_pos[SEQ*DMODEL];

// ---------------- helpers ----------------
__device__ __forceinline__ float tf32r(float v) {
    float o; asm("cvt.rna.tf32.f32 %0, %1;" : "=f"(o) : "f"(v)); return o;
}
__device__ __forceinline__ uint32_t fbits(float v) { return __float_as_uint(v); }

__device__ __forceinline__ void mma1688(float c[4], const uint32_t a[4], const uint32_t b[2]) {
    asm volatile(
        "mma.sync.aligned.m16n8k8.row.col.f32.tf32.tf32.f32 "
        "{%0,%1,%2,%3}, {%4,%5,%6,%7}, {%8,%9}, {%0,%1,%2,%3};"
        : "+f"(c[0]), "+f"(c[1]), "+f"(c[2]), "+f"(c[3])
        : "r"(a[0]), "r"(a[1]), "r"(a[2]), "r"(a[3]), "r"(b[0]), "r"(b[1]));
}

// ---------------- tf32 mma GEMM: C[M,N] = act(alpha*A@B^T + bias) ----------------
// A [M,K] K-major, B [N,K] K-major. M,N mult of 128; K mult of 16.
// Block 128x128, 8 warps in 4(M) x 2(N), warp tile 32x64, BK=16.
#define BK    16
#define PADK  20                     // floats per smem row (conflict-free)
#define TILEF (128*PADK)             // floats per tile

template<bool SPLIT, int ACT, bool BIAS>
__global__ void __launch_bounds__(256, 1)
mma_gemm(const float* __restrict__ Ag, const float* __restrict__ Bg,
         const float* __restrict__ bias, float* __restrict__ Cg,
         int K, int N, float alpha,
         long long sA, long long sB, long long sC)
{
    extern __shared__ __align__(16) float sh[];
    const float* A = Ag + (long long)blockIdx.z * sA;
    const float* B = Bg + (long long)blockIdx.z * sB;
    float* C = Cg + (long long)blockIdx.z * sC;
    const int bm = blockIdx.y * 128, bn = blockIdx.x * 128;
    const int tid = threadIdx.x, lane = tid & 31, wid = tid >> 5;
    const int wm = wid & 3, wn = wid >> 2;      // 4 x 2 warp grid
    constexpr int NT = SPLIT ? 4 : 2;

    float acc[2][8][4];
    #pragma unroll
    for (int i = 0; i < 2; i++)
        #pragma unroll
        for (int j = 0; j < 8; j++)
            #pragma unroll
            for (int p = 0; p < 4; p++) acc[i][j][p] = 0.f;

    // staging: slot s in [0,512): row = s>>2, kq = s&3 (float4 along K)
    const int iters = K / BK;
    float4 va[2], vb[2];
    #pragma unroll
    for (int u = 0; u < 2; ++u) {
        const int s = tid + u * 256, row = s >> 2, kq = s & 3;
        va[u] = *(const float4*)(A + (long long)(bm + row) * K + kq * 4);
        vb[u] = *(const float4*)(B + (long long)(bn + row) * K + kq * 4);
    }

    for (int t = 0; t < iters; ++t) {
        float* base = sh + (t & 1) * NT * TILEF;
        float* as_h = base;
        float* bs_h = base + TILEF;
        float* as_l = base + 2 * TILEF;
        float* bs_l = base + 3 * TILEF;

        #pragma unroll
        for (int u = 0; u < 2; ++u) {
            const int s = tid + u * 256, row = s >> 2, kq = s & 3;
            const int off = row * PADK + kq * 4;
            if (SPLIT) {
                float4 h, l;
                h.x = tf32r(va[u].x); l.x = va[u].x - h.x;
                h.y = tf32r(va[u].y); l.y = va[u].y - h.y;
                h.z = tf32r(va[u].z); l.z = va[u].z - h.z;
                h.w = tf32r(va[u].w); l.w = va[u].w - h.w;
                *(float4*)(as_h + off) = h;
                *(float4*)(as_l + off) = l;
                h.x = tf32r(vb[u].x); l.x = vb[u].x - h.x;
                h.y = tf32r(vb[u].y); l.y = vb[u].y - h.y;
                h.z = tf32r(vb[u].z); l.z = vb[u].z - h.z;
                h.w = tf32r(vb[u].w); l.w = vb[u].w - h.w;
                *(float4*)(bs_h + off) = h;
                *(float4*)(bs_l + off) = l;
            } else {
                float4 h;
                h.x = tf32r(va[u].x); h.y = tf32r(va[u].y);
                h.z = tf32r(va[u].z); h.w = tf32r(va[u].w);
                *(float4*)(as_h + off) = h;
                h.x = tf32r(vb[u].x); h.y = tf32r(vb[u].y);
                h.z = tf32r(vb[u].z); h.w = tf32r(vb[u].w);
                *(float4*)(bs_h + off) = h;
            }
        }
        __syncthreads();

        if (t + 1 < iters) {
            const int k0 = (t + 1) * BK;
            #pragma unroll
            for (int u = 0; u < 2; ++u) {
                const int s = tid + u * 256, row = s >> 2, kq = s & 3;
                va[u] = *(const float4*)(A + (long long)(bm + row) * K + k0 + kq * 4);
                vb[u] = *(const float4*)(B + (long long)(bn + row) * K + k0 + kq * 4);
            }
        }

        #pragma unroll
        for (int ks = 0; ks < 2; ++ks) {
            const int kk = ks * 8 + (lane & 3);
            uint32_t a[2][4], al[2][4];
            #pragma unroll
            for (int i = 0; i < 2; ++i) {
                const int r0 = wm * 32 + i * 16 + (lane >> 2);
                a[i][0] = fbits(as_h[r0 * PADK + kk]);
                a[i][1] = fbits(as_h[(r0 + 8) * PADK + kk]);
                a[i][2] = fbits(as_h[r0 * PADK + kk + 4]);
                a[i][3] = fbits(as_h[(r0 + 8) * PADK + kk + 4]);
                if (SPLIT) {
                    al[i][0] = fbits(as_l[r0 * PADK + kk]);
                    al[i][1] = fbits(as_l[(r0 + 8) * PADK + kk]);
                    al[i][2] = fbits(as_l[r0 * PADK + kk + 4]);
                    al[i][3] = fbits(as_l[(r0 + 8) * PADK + kk + 4]);
                }
            }
            uint32_t b[8][2], bl[8][2];
            #pragma unroll
            for (int j = 0; j < 8; ++j) {
                const int c0 = wn * 64 + j * 8 + (lane >> 2);
                b[j][0] = fbits(bs_h[c0 * PADK + kk]);
                b[j][1] = fbits(bs_h[c0 * PADK + kk + 4]);
                if (SPLIT) {
                    bl[j][0] = fbits(bs_l[c0 * PADK + kk]);
                    bl[j][1] = fbits(bs_l[c0 * PADK + kk + 4]);
                }
            }
            #pragma unroll
            for (int i = 0; i < 2; ++i)
                #pragma unroll
                for (int j = 0; j < 8; ++j) {
                    mma1688(acc[i][j], a[i], b[j]);
                    if (SPLIT) {
                        mma1688(acc[i][j], a[i], bl[j]);
                        mma1688(acc[i][j], al[i], b[j]);
                    }
                }
        }
        __syncthreads();
    }

    // ---------------- epilogue ----------------
    #pragma unroll
    for (int i = 0; i < 2; ++i) {
        const int r0 = bm + wm * 32 + i * 16 + (lane >> 2);
        #pragma unroll
        for (int j = 0; j < 8; ++j) {
            const int c0 = bn + wn * 64 + j * 8 + (lane & 3) * 2;
            float v0 = acc[i][j][0] * alpha;
            float v1 = acc[i][j][1] * alpha;
            float v2 = acc[i][j][2] * alpha;
            float v3 = acc[i][j][3] * alpha;
            if (BIAS) {
                const float b0 = bias[c0], b1 = bias[c0 + 1];
                v0 += b0; v1 += b1; v2 += b0; v3 += b1;
            }
            if (ACT == 1) {
                v0 = 0.5f * v0 * (1.0f + erff(v0 * 0.7071067811865475f));
                v1 = 0.5f * v1 * (1.0f + erff(v1 * 0.7071067811865475f));
                v2 = 0.5f * v2 * (1.0f + erff(v2 * 0.7071067811865475f));
                v3 = 0.5f * v3 * (1.0f + erff(v3 * 0.7071067811865475f));
            }
            *(float2*)(C + (long long)r0 * N + c0)       = make_float2(v0, v1);
            *(float2*)(C + (long long)(r0 + 8) * N + c0) = make_float2(v2, v3);
        }
    }
}

// ---------------- transpose ----------------
__global__ void transpose_kernel(const float* __restrict__ in, float* __restrict__ out,
                                 int R, int Ccols, long long sIn, long long sOut)
{
    __shared__ float t[32][33];
    in  += (long long)blockIdx.z * sIn;
    out += (long long)blockIdx.z * sOut;
    const int c0 = blockIdx.x * 32, r0 = blockIdx.y * 32;
    #pragma unroll
    for (int j = 0; j < 32; j += 8)
        t[threadIdx.y + j][threadIdx.x] =
            in[(long long)(r0 + threadIdx.y + j) * Ccols + c0 + threadIdx.x];
    __syncthreads();
    #pragma unroll
    for (int j = 0; j < 32; j += 8)
        out[(long long)(c0 + threadIdx.y + j) * R + r0 + threadIdx.x] =
            t[threadIdx.x][threadIdx.y + j];
}

// ---------------- pos table + embedding ----------------
__global__ void pos_kernel(float* __restrict__ tab) {
    const int s = blockIdx.x;
    #pragma unroll
    for (int j = 0; j < 2; ++j) {
        const int d = threadIdx.x + j * 256;
        double ang = (double)s * exp(-(2.0 * (double)d / 512.0) * 9.210340371976184);
        tab[s * DMODEL + d] = (float)(((d & 1) == 0) ? sin(ang) : cos(ang));
    }
}

__global__ void embed_kernel(const int* __restrict__ seq, const float* __restrict__ emb,
                             const float* __restrict__ tab, float* __restrict__ x)
{
    const int row = blockIdx.x;
    const int s = row & (SEQ - 1);
    const int tok = seq[row];
    const int d0 = threadIdx.x * 4;
    const float sc = 22.627416997969522f;
    float4 e = *(const float4*)(emb + (long long)tok * DMODEL + d0);
    float4 p = *(const float4*)(tab + s * DMODEL + d0);
    float4 o = { (e.x + p.x) * sc, (e.y + p.y) * sc, (e.z + p.z) * sc, (e.w + p.w) * sc };
    *(float4*)(x + (long long)row * DMODEL + d0) = o;
}

// ---------------- block reductions ----------------
template<int NT>
__device__ __forceinline__ float blockSum(float v, float* sm) {
    #pragma unroll
    for (int o = 16; o > 0; o >>= 1) v += __shfl_xor_sync(0xffffffffu, v, o);
    const int w = threadIdx.x >> 5;
    if ((threadIdx.x & 31) == 0) sm[w] = v;
    __syncthreads();
    if (threadIdx.x < 32) {
        float x = (threadIdx.x < NT / 32) ? sm[threadIdx.x] : 0.f;
        #pragma unroll
        for (int o = NT / 64; o > 0; o >>= 1) x += __shfl_xor_sync(0xffffffffu, x, o);
        if (threadIdx.x == 0) sm[0] = x;
    }
    __syncthreads();
    float r = sm[0];
    __syncthreads();
    return r;
}
template<int NT>
__device__ __forceinline__ float blockMax(float v, float* sm) {
    #pragma unroll
    for (int o = 16; o > 0; o >>= 1) v = fmaxf(v, __shfl_xor_sync(0xffffffffu, v, o));
    const int w = threadIdx.x >> 5;
    if ((threadIdx.x & 31) == 0) sm[w] = v;
    __syncthreads();
    if (threadIdx.x < 32) {
        float x = (threadIdx.x < NT / 32) ? sm[threadIdx.x] : -INFINITY;
        #pragma unroll
        for (int o = NT / 64; o > 0; o >>= 1) x = fmaxf(x, __shfl_xor_sync(0xffffffffu, x, o));
        if (threadIdx.x == 0) sm[0] = x;
    }
    __syncthreads();
    float r = sm[0];
    __syncthreads();
    return r;
}

// ---------------- softmax ----------------
__global__ void softmax_kernel(float* __restrict__ S)
{
    __shared__ float sm[8];
    float* row = S + (long long)blockIdx.x * SEQ;
    const int t = threadIdx.x;
    float vals[8];
    float m = -INFINITY;
    #pragma unroll
    for (int i = 0; i < 8; i++) { vals[i] = row[t + i * 256]; m = fmaxf(m, vals[i]); }
    m = blockMax<256>(m, sm);
    float s = 0.f;
    #pragma unroll
    for (int i = 0; i < 8; i++) { vals[i] = expf(vals[i] - m); s += vals[i]; }
    s = blockSum<256>(s, sm);
    const float inv = 1.f / s;
    #pragma unroll
    for (int i = 0; i < 8; i++) row[t + i * 256] = vals[i] * inv;
}

// ---------------- fused add + LayerNorm ----------------
__global__ void add_ln_kernel(const float* __restrict__ a, const float* __restrict__ b,
                              const float* __restrict__ gamma, const float* __restrict__ beta,
                              float* __restrict__ out)
{
    __shared__ float sm[4];
    const long long base = (long long)blockIdx.x * DMODEL;
    const int d0 = threadIdx.x * 4;
    float4 av = *(const float4*)(a + base + d0);
    float4 bv = *(const float4*)(b + base + d0);
    float z[4] = { av.x + bv.x, av.y + bv.y, av.z + bv.z, av.w + bv.w };
    float s = z[0] + z[1] + z[2] + z[3];
    s = blockSum<128>(s, sm);
    const float mu = s * (1.0f / DMODEL);
    float vs = 0.f;
    #pragma unroll
    for (int i = 0; i < 4; i++) { float dz = z[i] - mu; vs += dz * dz; }
    vs = blockSum<128>(vs, sm);
    const float rstd = rsqrtf(vs * (1.0f / DMODEL) + 1e-5f);
    float4 gv = *(const float4*)(gamma + d0);
    float4 bvv = *(const float4*)(beta + d0);
    float4 o;
    o.x = (z[0] - mu) * rstd * gv.x + bvv.x;
    o.y = (z[1] - mu) * rstd * gv.y + bvv.y;
    o.z = (z[2] - mu) * rstd * gv.z + bvv.z;
    o.w = (z[3] - mu) * rstd * gv.w + bvv.w;
    *(float4*)(out + base + d0) = o;
}

// ---------------- launch ----------------
#define SMEM_STD   (2 * 2 * TILEF * 4)   // 40960
#define SMEM_SPLIT (2 * 4 * TILEF * 4)   // 81920

extern "C" void kernel_launch(void* const* d_in, const int* in_sizes, int n_in,
                              void* d_out, int out_size)
{
    const int*   seq  = (const int*)  d_in[0];
    const float* emb  = (const float*)d_in[1];
    const float* wk   = (const float*)d_in[2];
    const float* bk   = (const float*)d_in[3];
    const float* wq   = (const float*)d_in[4];
    const float* bq   = (const float*)d_in[5];
    const float* wv   = (const float*)d_in[6];
    const float* bv   = (const float*)d_in[7];
    const float* ln_g = (const float*)d_in[8];
    const float* ln_b = (const float*)d_in[9];
    const float* w1   = (const float*)d_in[10];
    const float* b1   = (const float*)d_in[11];
    const float* w2   = (const float*)d_in[12];
    const float* b2   = (const float*)d_in[13];
    float* out = (float*)d_out;

    float *x, *k, *q, *v, *vT, *at, *r, *f2, *sc, *f1;
    float *wkT, *wqT, *wvT, *w1T, *w2T, *pos;
    cudaGetSymbolAddress((void**)&x,   g_x);
    cudaGetSymbolAddress((void**)&k,   g_k);
    cudaGetSymbolAddress((void**)&q,   g_q);
    cudaGetSymbolAddress((void**)&v,   g_v);
    cudaGetSymbolAddress((void**)&vT,  g_vT);
    cudaGetSymbolAddress((void**)&at,  g_at);
    cudaGetSymbolAddress((void**)&r,   g_r);
    cudaGetSymbolAddress((void**)&f2,  g_f2);
    cudaGetSymbolAddress((void**)&sc,  g_sc);
    cudaGetSymbolAddress((void**)&f1,  g_f1);
    cudaGetSymbolAddress((void**)&wkT, g_wkT);
    cudaGetSymbolAddress((void**)&wqT, g_wqT);
    cudaGetSymbolAddress((void**)&wvT, g_wvT);
    cudaGetSymbolAddress((void**)&w1T, g_w1T);
    cudaGetSymbolAddress((void**)&w2T, g_w2T);
    cudaGetSymbolAddress((void**)&pos, g_pos);

    cudaFuncSetAttribute(mma_gemm<true,  0, true >, cudaFuncAttributeMaxDynamicSharedMemorySize, SMEM_SPLIT);
    cudaFuncSetAttribute(mma_gemm<true,  0, false>, cudaFuncAttributeMaxDynamicSharedMemorySize, SMEM_SPLIT);
    cudaFuncSetAttribute(mma_gemm<false, 0, true >, cudaFuncAttributeMaxDynamicSharedMemorySize, SMEM_STD);
    cudaFuncSetAttribute(mma_gemm<false, 0, false>, cudaFuncAttributeMaxDynamicSharedMemorySize, SMEM_STD);
    cudaFuncSetAttribute(mma_gemm<false, 1, true >, cudaFuncAttributeMaxDynamicSharedMemorySize, SMEM_STD);

    pos_kernel<<<SEQ, 256>>>(pos);
    embed_kernel<<<BSTOT, 128>>>(seq, emb, pos, x);

    dim3 tb(32, 8);
    transpose_kernel<<<dim3(16, 16, 1), tb>>>(wk, wkT, DMODEL, DMODEL, 0, 0);
    transpose_kernel<<<dim3(16, 16, 1), tb>>>(wq, wqT, DMODEL, DMODEL, 0, 0);
    transpose_kernel<<<dim3(16, 16, 1), tb>>>(wv, wvT, DMODEL, DMODEL, 0, 0);
    transpose_kernel<<<dim3(64, 16, 1), tb>>>(w1, w1T, DMODEL, DFFN, 0, 0);
    transpose_kernel<<<dim3(16, 64, 1), tb>>>(w2, w2T, DFFN, DMODEL, 0, 0);

    // projections (split precision for k,q — they feed the logits)
    mma_gemm<true,  0, true><<<dim3(4, 64, 1), 256, SMEM_SPLIT>>>(x, wkT, bk, k, DMODEL, DMODEL, 1.f, 0, 0, 0);
    mma_gemm<true,  0, true><<<dim3(4, 64, 1), 256, SMEM_SPLIT>>>(x, wqT, bq, q, DMODEL, DMODEL, 1.f, 0, 0, 0);
    mma_gemm<false, 0, true><<<dim3(4, 64, 1), 256, SMEM_STD  >>>(x, wvT, bv, v, DMODEL, DMODEL, 1.f, 0, 0, 0);

    transpose_kernel<<<dim3(16, 64, NBATCH), tb>>>(v, vT, SEQ, DMODEL,
        (long long)SEQ * DMODEL, (long long)DMODEL * SEQ);

    // scores = k @ q^T / sqrt(D)   (split precision)
    mma_gemm<true, 0, false><<<dim3(16, 16, NBATCH), 256, SMEM_SPLIT>>>(
        k, q, nullptr, sc, DMODEL, SEQ, 0.044194173824159216f,
        (long long)SEQ * DMODEL, (long long)SEQ * DMODEL, (long long)SEQ * SEQ);

    softmax_kernel<<<NBATCH * SEQ, 256>>>(sc);

    // attn = P @ V
    mma_gemm<false, 0, false><<<dim3(4, 16, NBATCH), 256, SMEM_STD>>>(
        sc, vT, nullptr, at, SEQ, DMODEL, 1.f,
        (long long)SEQ * SEQ, (long long)DMODEL * SEQ, (long long)SEQ * DMODEL);

    add_ln_kernel<<<BSTOT, 128>>>(x, at, ln_g, ln_b, r);

    // FFN
    mma_gemm<false, 1, true><<<dim3(16, 64, 1), 256, SMEM_STD>>>(r, w1T, b1, f1, DMODEL, DFFN, 1.f, 0, 0, 0);
    mma_gemm<false, 0, true><<<dim3(4, 64, 1), 256, SMEM_STD>>>(f1, w2T, b2, f2, DFFN, DMODEL, 1.f, 0, 0, 0);

    add_ln_kernel<<<BSTOT, 128>>>(r, f2, ln_g, ln_b, out);
}

// round 4
// speedup vs baseline: 2.3975x; 1.4796x over previous
#include <cuda_runtime.h>
#include <cuda_bf16.h>
#include <cstdint>
#include <math.h>

#define NBATCH 4
#define SEQ    2048
#define DMODEL 512
#define DFFN   2048
#define BSTOT  (NBATCH*SEQ)

// ---------------- scratch ----------------
__device__ __align__(256) float g_x [BSTOT*DMODEL];
__device__ __align__(256) float g_v [BSTOT*DMODEL];
__device__ __align__(256) float g_at[BSTOT*DMODEL];
__device__ __align__(256) float g_r [BSTOT*DMODEL];
__device__ __align__(256) float g_f2[BSTOT*DMODEL];
__device__ __align__(256) float g_sc[(long long)NBATCH*SEQ*SEQ];
__device__ __align__(256) float g_pos[SEQ*DMODEL];

__device__ __align__(256) __nv_bfloat16 g_xh[BSTOT*DMODEL];
__device__ __align__(256) __nv_bfloat16 g_xl[BSTOT*DMODEL];
__device__ __align__(256) __nv_bfloat16 g_kh[BSTOT*DMODEL];
__device__ __align__(256) __nv_bfloat16 g_kl[BSTOT*DMODEL];
__device__ __align__(256) __nv_bfloat16 g_qh[BSTOT*DMODEL];
__device__ __align__(256) __nv_bfloat16 g_ql[BSTOT*DMODEL];
__device__ __align__(256) __nv_bfloat16 g_vTh[BSTOT*DMODEL];
__device__ __align__(256) __nv_bfloat16 g_vTl[BSTOT*DMODEL];
__device__ __align__(256) __nv_bfloat16 g_rh[BSTOT*DMODEL];
__device__ __align__(256) __nv_bfloat16 g_rl[BSTOT*DMODEL];
__device__ __align__(256) __nv_bfloat16 g_ph[(long long)NBATCH*SEQ*SEQ];
__device__ __align__(256) __nv_bfloat16 g_pl[(long long)NBATCH*SEQ*SEQ];
__device__ __align__(256) __nv_bfloat16 g_f1h[(long long)BSTOT*DFFN];
__device__ __align__(256) __nv_bfloat16 g_f1l[(long long)BSTOT*DFFN];
__device__ __align__(256) __nv_bfloat16 g_wkTh[DMODEL*DMODEL];
__device__ __align__(256) __nv_bfloat16 g_wkTl[DMODEL*DMODEL];
__device__ __align__(256) __nv_bfloat16 g_wqTh[DMODEL*DMODEL];
__device__ __align__(256) __nv_bfloat16 g_wqTl[DMODEL*DMODEL];
__device__ __align__(256) __nv_bfloat16 g_wvTh[DMODEL*DMODEL];
__device__ __align__(256) __nv_bfloat16 g_wvTl[DMODEL*DMODEL];
__device__ __align__(256) __nv_bfloat16 g_w1Th[DFFN*DMODEL];
__device__ __align__(256) __nv_bfloat16 g_w1Tl[DFFN*DMODEL];
__device__ __align__(256) __nv_bfloat16 g_w2Th[DMODEL*DFFN];
__device__ __align__(256) __nv_bfloat16 g_w2Tl[DMODEL*DFFN];

// ---------------- helpers ----------------
__device__ __forceinline__ uint32_t smem_u32(const void* p) {
    uint32_t a;
    asm("{ .reg .u64 t; cvta.to.shared.u64 t, %1; cvt.u32.u64 %0, t; }" : "=r"(a) : "l"(p));
    return a;
}
__device__ __forceinline__ void mmabf16(float c[4], const uint32_t a[4], const uint32_t b[2]) {
    asm volatile(
        "mma.sync.aligned.m16n8k16.row.col.f32.bf16.bf16.f32 "
        "{%0,%1,%2,%3}, {%4,%5,%6,%7}, {%8,%9}, {%0,%1,%2,%3};"
        : "+f"(c[0]), "+f"(c[1]), "+f"(c[2]), "+f"(c[3])
        : "r"(a[0]), "r"(a[1]), "r"(a[2]), "r"(a[3]), "r"(b[0]), "r"(b[1]));
}
__device__ __forceinline__ void split2(float v0, float v1, __nv_bfloat162& h, __nv_bfloat162& l) {
    __nv_bfloat16 h0 = __float2bfloat16(v0), h1 = __float2bfloat16(v1);
    h.x = h0; h.y = h1;
    l.x = __float2bfloat16(v0 - __bfloat162float(h0));
    l.y = __float2bfloat16(v1 - __bfloat162float(h1));
}

// ---------------- bf16x3 GEMM ----------------
// C[M,N] = act(alpha*(A@B^T) + bias), A=(Ah+Al)[M,K] K-major, B=(Bh+Bl)[N,K] K-major
// block 256x128, BK=32, 8 warps (4M x 2N), warp tile 64x64, 3-stage cp.async.
#define STAGE_BYTES 49152      // Ah 16K | Al 16K | Bh 8K | Bl 8K
#define SMEM_TOT    (3*STAGE_BYTES)

__device__ __forceinline__ void issue_tile(
    uint32_t sstage,
    const __nv_bfloat16* __restrict__ Ah, const __nv_bfloat16* __restrict__ Al,
    const __nv_bfloat16* __restrict__ Bh, const __nv_bfloat16* __restrict__ Bl,
    int bm, int bn, int K, int k0, int tid)
{
    #pragma unroll
    for (int t = 0; t < 12; ++t) {
        const int c = tid + t * 256;
        const __nv_bfloat16* src;
        uint32_t off;
        if (c < 2048) {                       // A tiles: 256 rows x 4 chunks x2
            const int tile = c >> 10, cc = c & 1023, row = cc >> 2, ch = cc & 3;
            src = (tile ? Al : Ah) + (long long)(bm + row) * K + k0 + ch * 8;
            off = tile * 16384 + row * 64 + ((ch ^ ((row >> 1) & 3)) << 4);
        } else {                              // B tiles: 128 rows x 4 chunks x2
            const int c2 = c - 2048, tile = c2 >> 9, cc = c2 & 511, row = cc >> 2, ch = cc & 3;
            src = (tile ? Bl : Bh) + (long long)(bn + row) * K + k0 + ch * 8;
            off = 32768 + tile * 8192 + row * 64 + ((ch ^ ((row >> 1) & 3)) << 4);
        }
        asm volatile("cp.async.cg.shared.global [%0], [%1], 16;"
                     :: "r"(sstage + off), "l"(src));
    }
}

template<int ACT, bool BIAS, bool OUTF32, bool OUTPAIR>
__global__ void __launch_bounds__(256, 1)
bf16_gemm(const __nv_bfloat16* __restrict__ Ah, const __nv_bfloat16* __restrict__ Al,
          const __nv_bfloat16* __restrict__ Bh, const __nv_bfloat16* __restrict__ Bl,
          const float* __restrict__ bias, float* __restrict__ Cf,
          __nv_bfloat16* __restrict__ Ch, __nv_bfloat16* __restrict__ Cl,
          int K, int N, float alpha,
          long long sA, long long sB, long long sC)
{
    extern __shared__ __align__(16) char smem[];
    Ah += (long long)blockIdx.z * sA; Al += (long long)blockIdx.z * sA;
    Bh += (long long)blockIdx.z * sB; Bl += (long long)blockIdx.z * sB;
    const int bm = blockIdx.y * 256, bn = blockIdx.x * 128;
    const int tid = threadIdx.x, lane = tid & 31, wid = tid >> 5;
    const int wm = wid & 3, wn = wid >> 2;   // 4(M) x 2(N)
    const uint32_t sb = smem_u32(smem);

    float acc[4][8][4];
    #pragma unroll
    for (int i = 0; i < 4; i++)
        #pragma unroll
        for (int j = 0; j < 8; j++)
            #pragma unroll
            for (int p = 0; p < 4; p++) acc[i][j][p] = 0.f;

    const int iters = K >> 5;
    issue_tile(sb, Ah, Al, Bh, Bl, bm, bn, K, 0, tid);
    asm volatile("cp.async.commit_group;" ::: "memory");
    issue_tile(sb + STAGE_BYTES, Ah, Al, Bh, Bl, bm, bn, K, 32, tid);
    asm volatile("cp.async.commit_group;" ::: "memory");

    for (int t = 0; t < iters; ++t) {
        asm volatile("cp.async.wait_group 1;" ::: "memory");
        __syncthreads();
        if (t + 2 < iters)
            issue_tile(sb + ((t + 2) % 3) * STAGE_BYTES, Ah, Al, Bh, Bl,
                       bm, bn, K, (t + 2) * 32, tid);
        asm volatile("cp.async.commit_group;" ::: "memory");

        const uint32_t* st = (const uint32_t*)(smem + (t % 3) * STAGE_BYTES);
        #pragma unroll
        for (int ks = 0; ks < 2; ++ks) {
            const int wlo = ks * 8 + (lane & 3);
            uint32_t ah[4][4], al2[4][4];
            #pragma unroll
            for (int i = 0; i < 4; ++i) {
                const int r0 = wm * 64 + i * 16 + (lane >> 2);
                const int r1 = r0 + 8;
                const int s0 = ((r0 >> 1) & 3) << 2;
                const int s1 = ((r1 >> 1) & 3) << 2;
                const uint32_t* A0 = st + r0 * 16;
                const uint32_t* A1 = st + r1 * 16;
                ah[i][0] = A0[wlo ^ s0];
                ah[i][1] = A1[wlo ^ s1];
                ah[i][2] = A0[(wlo + 4) ^ s0];
                ah[i][3] = A1[(wlo + 4) ^ s1];
                al2[i][0] = A0[4096 + (wlo ^ s0)];
                al2[i][1] = A1[4096 + (wlo ^ s1)];
                al2[i][2] = A0[4096 + ((wlo + 4) ^ s0)];
                al2[i][3] = A1[4096 + ((wlo + 4) ^ s1)];
            }
            #pragma unroll
            for (int j = 0; j < 8; ++j) {
                const int n0 = wn * 64 + j * 8 + (lane >> 2);
                const int sn = ((n0 >> 1) & 3) << 2;
                const uint32_t* B0 = st + 8192 + n0 * 16;
                uint32_t bh[2], bl[2];
                bh[0] = B0[wlo ^ sn];
                bh[1] = B0[(wlo + 4) ^ sn];
                bl[0] = B0[2048 + (wlo ^ sn)];
                bl[1] = B0[2048 + ((wlo + 4) ^ sn)];
                #pragma unroll
                for (int i = 0; i < 4; ++i) {
                    mmabf16(acc[i][j], ah[i], bh);
                    mmabf16(acc[i][j], ah[i], bl);
                    mmabf16(acc[i][j], al2[i], bh);
                }
            }
        }
        __syncthreads();
    }

    // ---------------- epilogue ----------------
    #pragma unroll
    for (int i = 0; i < 4; ++i) {
        const long long r0 = bm + wm * 64 + i * 16 + (lane >> 2);
        #pragma unroll
        for (int j = 0; j < 8; ++j) {
            const int c0 = bn + wn * 64 + j * 8 + (lane & 3) * 2;
            float v0 = acc[i][j][0] * alpha;
            float v1 = acc[i][j][1] * alpha;
            float v2 = acc[i][j][2] * alpha;
            float v3 = acc[i][j][3] * alpha;
            if (BIAS) {
                float2 bb = *(const float2*)(bias + c0);
                v0 += bb.x; v1 += bb.y; v2 += bb.x; v3 += bb.y;
            }
            if (ACT == 1) {
                v0 = 0.5f * v0 * (1.0f + erff(v0 * 0.7071067811865475f));
                v1 = 0.5f * v1 * (1.0f + erff(v1 * 0.7071067811865475f));
                v2 = 0.5f * v2 * (1.0f + erff(v2 * 0.7071067811865475f));
                v3 = 0.5f * v3 * (1.0f + erff(v3 * 0.7071067811865475f));
            }
            const long long o0 = (r0 + blockIdx.z * (sC == 0 ? 0 : 0)) * 0; (void)o0;
            float* cf0 = Cf + (long long)blockIdx.z * sC + r0 * N + c0;
            float* cf1 = cf0 + 8LL * N;
            if (OUTF32) {
                *(float2*)cf0 = make_float2(v0, v1);
                *(float2*)cf1 = make_float2(v2, v3);
            }
            if (OUTPAIR) {
                __nv_bfloat162 h, l;
                long long off0 = (long long)blockIdx.z * sC + r0 * N + c0;
                long long off1 = off0 + 8LL * N;
                split2(v0, v1, h, l);
                *(__nv_bfloat162*)(Ch + off0) = h;
                *(__nv_bfloat162*)(Cl + off0) = l;
                split2(v2, v3, h, l);
                *(__nv_bfloat162*)(Ch + off1) = h;
                *(__nv_bfloat162*)(Cl + off1) = l;
            }
        }
    }
}

// ---------------- transpose + convert-to-pairs: in fp32 [R,C] -> out pairs [C,R] ----------------
__global__ void transpose_convert(const float* __restrict__ in,
                                  __nv_bfloat16* __restrict__ oh, __nv_bfloat16* __restrict__ ol,
                                  int R, int C, long long sIn, long long sOut)
{
    __shared__ float t[32][33];
    in += (long long)blockIdx.z * sIn;
    oh += (long long)blockIdx.z * sOut;
    ol += (long long)blockIdx.z * sOut;
    const int c0 = blockIdx.x * 32, r0 = blockIdx.y * 32;
    #pragma unroll
    for (int j = 0; j < 32; j += 8)
        t[threadIdx.y + j][threadIdx.x] =
            in[(long long)(r0 + threadIdx.y + j) * C + c0 + threadIdx.x];
    __syncthreads();
    #pragma unroll
    for (int j = 0; j < 32; j += 8) {
        const float v = t[threadIdx.x][threadIdx.y + j];
        const __nv_bfloat16 h = __float2bfloat16(v);
        const long long o = (long long)(c0 + threadIdx.y + j) * R + r0 + threadIdx.x;
        oh[o] = h;
        ol[o] = __float2bfloat16(v - __bfloat162float(h));
    }
}

// ---------------- pos + embedding ----------------
__global__ void pos_kernel(float* __restrict__ tab) {
    const int s = blockIdx.x;
    #pragma unroll
    for (int j = 0; j < 2; ++j) {
        const int d = threadIdx.x + j * 256;
        double ang = (double)s * exp(-(2.0 * (double)d / 512.0) * 9.210340371976184);
        tab[s * DMODEL + d] = (float)(((d & 1) == 0) ? sin(ang) : cos(ang));
    }
}

__global__ void embed_kernel(const int* __restrict__ seq, const float* __restrict__ emb,
                             const float* __restrict__ tab, float* __restrict__ x,
                             __nv_bfloat16* __restrict__ xh, __nv_bfloat16* __restrict__ xl)
{
    const int row = blockIdx.x;
    const int s = row & (SEQ - 1);
    const int tok = seq[row];
    const int d0 = threadIdx.x * 4;
    const float sc = 22.627416997969522f;
    float4 e = *(const float4*)(emb + (long long)tok * DMODEL + d0);
    float4 p = *(const float4*)(tab + s * DMODEL + d0);
    float4 o = { (e.x + p.x) * sc, (e.y + p.y) * sc, (e.z + p.z) * sc, (e.w + p.w) * sc };
    const long long base = (long long)row * DMODEL + d0;
    *(float4*)(x + base) = o;
    __nv_bfloat162 h, l;
    split2(o.x, o.y, h, l);
    *(__nv_bfloat162*)(xh + base) = h;
    *(__nv_bfloat162*)(xl + base) = l;
    split2(o.z, o.w, h, l);
    *(__nv_bfloat162*)(xh + base + 2) = h;
    *(__nv_bfloat162*)(xl + base + 2) = l;
}

// ---------------- block reductions ----------------
template<int NT>
__device__ __forceinline__ float blockSum(float v, float* sm) {
    #pragma unroll
    for (int o = 16; o > 0; o >>= 1) v += __shfl_xor_sync(0xffffffffu, v, o);
    const int w = threadIdx.x >> 5;
    if ((threadIdx.x & 31) == 0) sm[w] = v;
    __syncthreads();
    if (threadIdx.x < 32) {
        float x = (threadIdx.x < NT / 32) ? sm[threadIdx.x] : 0.f;
        #pragma unroll
        for (int o = NT / 64; o > 0; o >>= 1) x += __shfl_xor_sync(0xffffffffu, x, o);
        if (threadIdx.x == 0) sm[0] = x;
    }
    __syncthreads();
    float r = sm[0];
    __syncthreads();
    return r;
}
template<int NT>
__device__ __forceinline__ float blockMax(float v, float* sm) {
    #pragma unroll
    for (int o = 16; o > 0; o >>= 1) v = fmaxf(v, __shfl_xor_sync(0xffffffffu, v, o));
    const int w = threadIdx.x >> 5;
    if ((threadIdx.x & 31) == 0) sm[w] = v;
    __syncthreads();
    if (threadIdx.x < 32) {
        float x = (threadIdx.x < NT / 32) ? sm[threadIdx.x] : -INFINITY;
        #pragma unroll
        for (int o = NT / 64; o > 0; o >>= 1) x = fmaxf(x, __shfl_xor_sync(0xffffffffu, x, o));
        if (threadIdx.x == 0) sm[0] = x;
    }
    __syncthreads();
    float r = sm[0];
    __syncthreads();
    return r;
}

// ---------------- softmax (fp32 in, bf16 pairs out) ----------------
__global__ void softmax_kernel(const float* __restrict__ S,
                               __nv_bfloat16* __restrict__ ph, __nv_bfloat16* __restrict__ pl)
{
    __shared__ float sm[8];
    const long long base = (long long)blockIdx.x * SEQ;
    const float* row = S + base;
    const int t = threadIdx.x;
    float vals[8];
    float m = -INFINITY;
    #pragma unroll
    for (int i = 0; i < 8; i++) { vals[i] = row[t + i * 256]; m = fmaxf(m, vals[i]); }
    m = blockMax<256>(m, sm);
    float s = 0.f;
    #pragma unroll
    for (int i = 0; i < 8; i++) { vals[i] = expf(vals[i] - m); s += vals[i]; }
    s = blockSum<256>(s, sm);
    const float inv = 1.f / s;
    #pragma unroll
    for (int i = 0; i < 8; i++) {
        const float p = vals[i] * inv;
        const __nv_bfloat16 h = __float2bfloat16(p);
        ph[base + t + i * 256] = h;
        pl[base + t + i * 256] = __float2bfloat16(p - __bfloat162float(h));
    }
}

// ---------------- fused add + LayerNorm ----------------
template<bool PAIR>
__global__ void add_ln_kernel(const float* __restrict__ a, const float* __restrict__ b,
                              const float* __restrict__ gamma, const float* __restrict__ beta,
                              float* __restrict__ out,
                              __nv_bfloat16* __restrict__ oh, __nv_bfloat16* __restrict__ ol)
{
    __shared__ float sm[4];
    const long long base = (long long)blockIdx.x * DMODEL;
    const int d0 = threadIdx.x * 4;
    float4 av = *(const float4*)(a + base + d0);
    float4 bv = *(const float4*)(b + base + d0);
    float z[4] = { av.x + bv.x, av.y + bv.y, av.z + bv.z, av.w + bv.w };
    float s = z[0] + z[1] + z[2] + z[3];
    s = blockSum<128>(s, sm);
    const float mu = s * (1.0f / DMODEL);
    float vs = 0.f;
    #pragma unroll
    for (int i = 0; i < 4; i++) { float dz = z[i] - mu; vs += dz * dz; }
    vs = blockSum<128>(vs, sm);
    const float rstd = rsqrtf(vs * (1.0f / DMODEL) + 1e-5f);
    float4 gv = *(const float4*)(gamma + d0);
    float4 bvv = *(const float4*)(beta + d0);
    float4 o;
    o.x = (z[0] - mu) * rstd * gv.x + bvv.x;
    o.y = (z[1] - mu) * rstd * gv.y + bvv.y;
    o.z = (z[2] - mu) * rstd * gv.z + bvv.z;
    o.w = (z[3] - mu) * rstd * gv.w + bvv.w;
    *(float4*)(out + base + d0) = o;
    if (PAIR) {
        __nv_bfloat162 h, l;
        split2(o.x, o.y, h, l);
        *(__nv_bfloat162*)(oh + base + d0) = h;
        *(__nv_bfloat162*)(ol + base + d0) = l;
        split2(o.z, o.w, h, l);
        *(__nv_bfloat162*)(oh + base + d0 + 2) = h;
        *(__nv_bfloat162*)(ol + base + d0 + 2) = l;
    }
}

// ---------------- launch ----------------
extern "C" void kernel_launch(void* const* d_in, const int* in_sizes, int n_in,
                              void* d_out, int out_size)
{
    const int*   seq  = (const int*)  d_in[0];
    const float* emb  = (const float*)d_in[1];
    const float* wk   = (const float*)d_in[2];
    const float* bk   = (const float*)d_in[3];
    const float* wq   = (const float*)d_in[4];
    const float* bq   = (const float*)d_in[5];
    const float* wv   = (const float*)d_in[6];
    const float* bv   = (const float*)d_in[7];
    const float* ln_g = (const float*)d_in[8];
    const float* ln_b = (const float*)d_in[9];
    const float* w1   = (const float*)d_in[10];
    const float* b1   = (const float*)d_in[11];
    const float* w2   = (const float*)d_in[12];
    const float* b2   = (const float*)d_in[13];
    float* out = (float*)d_out;

    float *x, *v, *at, *r, *f2, *sc, *pos;
    __nv_bfloat16 *xh, *xl, *kh, *kl, *qh, *ql, *vTh, *vTl, *rh, *rl, *ph, *pl, *f1h, *f1l;
    __nv_bfloat16 *wkTh, *wkTl, *wqTh, *wqTl, *wvTh, *wvTl, *w1Th, *w1Tl, *w2Th, *w2Tl;
    cudaGetSymbolAddress((void**)&x,    g_x);
    cudaGetSymbolAddress((void**)&v,    g_v);
    cudaGetSymbolAddress((void**)&at,   g_at);
    cudaGetSymbolAddress((void**)&r,    g_r);
    cudaGetSymbolAddress((void**)&f2,   g_f2);
    cudaGetSymbolAddress((void**)&sc,   g_sc);
    cudaGetSymbolAddress((void**)&pos,  g_pos);
    cudaGetSymbolAddress((void**)&xh,   g_xh);
    cudaGetSymbolAddress((void**)&xl,   g_xl);
    cudaGetSymbolAddress((void**)&kh,   g_kh);
    cudaGetSymbolAddress((void**)&kl,   g_kl);
    cudaGetSymbolAddress((void**)&qh,   g_qh);
    cudaGetSymbolAddress((void**)&ql,   g_ql);
    cudaGetSymbolAddress((void**)&vTh,  g_vTh);
    cudaGetSymbolAddress((void**)&vTl,  g_vTl);
    cudaGetSymbolAddress((void**)&rh,   g_rh);
    cudaGetSymbolAddress((void**)&rl,   g_rl);
    cudaGetSymbolAddress((void**)&ph,   g_ph);
    cudaGetSymbolAddress((void**)&pl,   g_pl);
    cudaGetSymbolAddress((void**)&f1h,  g_f1h);
    cudaGetSymbolAddress((void**)&f1l,  g_f1l);
    cudaGetSymbolAddress((void**)&wkTh, g_wkTh);
    cudaGetSymbolAddress((void**)&wkTl, g_wkTl);
    cudaGetSymbolAddress((void**)&wqTh, g_wqTh);
    cudaGetSymbolAddress((void**)&wqTl, g_wqTl);
    cudaGetSymbolAddress((void**)&wvTh, g_wvTh);
    cudaGetSymbolAddress((void**)&wvTl, g_wvTl);
    cudaGetSymbolAddress((void**)&w1Th, g_w1Th);
    cudaGetSymbolAddress((void**)&w1Tl, g_w1Tl);
    cudaGetSymbolAddress((void**)&w2Th, g_w2Th);
    cudaGetSymbolAddress((void**)&w2Tl, g_w2Tl);

    cudaFuncSetAttribute(bf16_gemm<0, true,  false, true >, cudaFuncAttributeMaxDynamicSharedMemorySize, SMEM_TOT);
    cudaFuncSetAttribute(bf16_gemm<0, true,  true,  false>, cudaFuncAttributeMaxDynamicSharedMemorySize, SMEM_TOT);
    cudaFuncSetAttribute(bf16_gemm<0, false, true,  false>, cudaFuncAttributeMaxDynamicSharedMemorySize, SMEM_TOT);
    cudaFuncSetAttribute(bf16_gemm<1, true,  false, true >, cudaFuncAttributeMaxDynamicSharedMemorySize, SMEM_TOT);

    // x = (emb[seq] + pos) * sqrt(D), plus bf16 pair form
    pos_kernel<<<SEQ, 256>>>(pos);
    embed_kernel<<<BSTOT, 128>>>(seq, emb, pos, x, xh, xl);

    // weights -> K-major bf16 pairs
    dim3 tb(32, 8);
    transpose_convert<<<dim3(16, 16, 1), tb>>>(wk, wkTh, wkTl, DMODEL, DMODEL, 0, 0);
    transpose_convert<<<dim3(16, 16, 1), tb>>>(wq, wqTh, wqTl, DMODEL, DMODEL, 0, 0);
    transpose_convert<<<dim3(16, 16, 1), tb>>>(wv, wvTh, wvTl, DMODEL, DMODEL, 0, 0);
    transpose_convert<<<dim3(64, 16, 1), tb>>>(w1, w1Th, w1Tl, DMODEL, DFFN, 0, 0);
    transpose_convert<<<dim3(16, 64, 1), tb>>>(w2, w2Th, w2Tl, DFFN, DMODEL, 0, 0);

    // projections
    bf16_gemm<0, true, false, true><<<dim3(4, 32, 1), 256, SMEM_TOT>>>(
        xh, xl, wkTh, wkTl, bk, nullptr, kh, kl, DMODEL, DMODEL, 1.f, 0, 0, 0);
    bf16_gemm<0, true, false, true><<<dim3(4, 32, 1), 256, SMEM_TOT>>>(
        xh, xl, wqTh, wqTl, bq, nullptr, qh, ql, DMODEL, DMODEL, 1.f, 0, 0, 0);
    bf16_gemm<0, true, true, false><<<dim3(4, 32, 1), 256, SMEM_TOT>>>(
        xh, xl, wvTh, wvTl, bv, v, nullptr, nullptr, DMODEL, DMODEL, 1.f, 0, 0, 0);

    // v[S,D] -> vT[D,S] pairs, per batch
    transpose_convert<<<dim3(16, 64, NBATCH), tb>>>(v, vTh, vTl, SEQ, DMODEL,
        (long long)SEQ * DMODEL, (long long)DMODEL * SEQ);

    // scores = k @ q^T / sqrt(D)
    bf16_gemm<0, false, true, false><<<dim3(16, 8, NBATCH), 256, SMEM_TOT>>>(
        kh, kl, qh, ql, nullptr, sc, nullptr, nullptr, DMODEL, SEQ, 0.044194173824159216f,
        (long long)SEQ * DMODEL, (long long)SEQ * DMODEL, (long long)SEQ * SEQ);

    softmax_kernel<<<NBATCH * SEQ, 256>>>(sc, ph, pl);

    // attn = P @ V
    bf16_gemm<0, false, true, false><<<dim3(4, 8, NBATCH), 256, SMEM_TOT>>>(
        ph, pl, vTh, vTl, nullptr, at, nullptr, nullptr, SEQ, DMODEL, 1.f,
        (long long)SEQ * SEQ, (long long)DMODEL * SEQ, (long long)SEQ * DMODEL);

    add_ln_kernel<true><<<BSTOT, 128>>>(x, at, ln_g, ln_b, r, rh, rl);

    // FFN
    bf16_gemm<1, true, false, true><<<dim3(16, 32, 1), 256, SMEM_TOT>>>(
        rh, rl, w1Th, w1Tl, b1, nullptr, f1h, f1l, DMODEL, DFFN, 1.f, 0, 0, 0);
    bf16_gemm<0, true, true, false><<<dim3(4, 32, 1), 256, SMEM_TOT>>>(
        f1h, f1l, w2Th, w2Tl, b2, f2, nullptr, nullptr, DFFN, DMODEL, 1.f, 0, 0, 0);

    add_ln_kernel<false><<<BSTOT, 128>>>(r, f2, ln_g, ln_b, out, nullptr, nullptr);
}